// round 17
// baseline (speedup 1.0000x reference)
#include <cuda_runtime.h>
#include <cstdint>

#define BATCH 8

// B in mma-fragment order: [t(9)][kk(8)][ni(8)][lane(32)] -> float2 {w(k), w(k+4)}
__device__ float2 g_bf[9 * 8 * 8 * 32];

__global__ void prep_w(const float* __restrict__ conv) {
    int idx = blockIdx.x * 256 + threadIdx.x;          // 18432 fragments
    if (idx < 18432) {
        int lane = idx & 31;
        int ni   = (idx >> 5) & 7;
        int kk   = (idx >> 8) & 7;
        int t    = idx >> 11;
        int oc  = ni * 8 + (lane >> 2);
        int ch0 = kk * 8 + (lane & 3);
        float w0 = conv[(oc * 64 + ch0) * 9 + t];
        float w1 = conv[(oc * 64 + ch0 + 4) * 9 + t];
        uint32_t v0, v1;
        asm("cvt.rna.tf32.f32 %0, %1;" : "=r"(v0) : "f"(w0));
        asm("cvt.rna.tf32.f32 %0, %1;" : "=r"(v1) : "f"(w1));
        g_bf[idx] = make_float2(__uint_as_float(v0), __uint_as_float(v1));
    }
}

static __device__ __forceinline__ void mma_tf32(float* d, const uint32_t* a,
                                                uint32_t b0, uint32_t b1) {
    asm volatile(
        "mma.sync.aligned.m16n8k8.row.col.f32.tf32.tf32.f32 "
        "{%0,%1,%2,%3}, {%4,%5,%6,%7}, {%8,%9}, {%0,%1,%2,%3};"
        : "+f"(d[0]), "+f"(d[1]), "+f"(d[2]), "+f"(d[3])
        : "r"(a[0]), "r"(a[1]), "r"(a[2]), "r"(a[3]), "r"(b0), "r"(b1));
}

__global__ __launch_bounds__(256, 2) void iconv_mma(
    const float* __restrict__ inp, const float* __restrict__ mask,
    const float* __restrict__ bias, float* __restrict__ out,
    float* __restrict__ mout)
{
    __shared__ float As[64 * 132];       // one raw input row [ch][pxcol]; reused by epilogue
    __shared__ unsigned s_mbits[256];    // 2 rows x 128 px
    __shared__ float s_nrm[256];
    __shared__ float s_bias[64];

    const int tid  = threadIdx.x;
    const int lane = tid & 31;
    const int wp   = tid >> 5;
    const int b    = blockIdx.x >> 6;
    const int y0   = (blockIdx.x & 63) << 1;           // row pair

    const int row_sel = wp >> 2;                       // warp's output row (0/1)
    const int yw      = y0 + row_sel;
    const int px0     = (wp & 3) * 32;
    const int rr      = lane >> 2;
    const int cc      = lane & 3;

    // ---- per-pixel mask bits, renorm, mask_out (tid = row*128 + px) ----
    {
        int prow = tid >> 7, x = tid & 127, y = y0 + prow;
        float m0 = mask[(b * 128 + y) * 128 + x];
        unsigned mbits = 0; float cnt = 0.f;
#pragma unroll
        for (int t = 0; t < 9; t++) {
            int yy = y + t / 3 - 1, xx = x + t % 3 - 1;
            float nb = ((unsigned)yy < 128u && (unsigned)xx < 128u)
                           ? mask[(b * 128 + yy) * 128 + xx] : -1.f;
            if (nb == m0) { mbits |= 1u << t; cnt += 1.f; }
        }
        s_mbits[tid] = mbits;
        s_nrm[tid]   = 9.f / cnt;                      // center always matches
        mout[(b * 128 + y) * 128 + x] = m0;
    }
    if (tid < 64) s_bias[tid] = bias[tid];
    // permanent zero halo columns (xx = -1 / 128)
    if (tid < 64)                   As[tid * 132]              = 0.f;
    else if (tid < 128)             As[(tid - 64) * 132 + 129] = 0.f;

    float acc[2][8][4];
#pragma unroll
    for (int mi = 0; mi < 2; mi++)
#pragma unroll
        for (int ni = 0; ni < 8; ni++)
#pragma unroll
            for (int r = 0; r < 4; r++) acc[mi][ni][r] = 0.f;

    // ---- 4 input-row phases ----
    for (int r = 0; r < 4; r++) {
        const int ir = y0 - 1 + r;                     // input row
        if ((unsigned)ir >= 128u) continue;            // gates are 0 for those taps

        __syncthreads();                               // prior phase done with As
        {   // 256 threads load raw row ir: px = tid&127, 32 channels each
            const int px = tid & 127, half = tid >> 7;
            const float* ip = inp + (((size_t)b * 64 + half * 32) * 128 + ir) * 128 + px;
            float* dst = As + (half * 32) * 132 + px + 1;
#pragma unroll
            for (int c = 0; c < 32; c++) {
                uint32_t tv;
                float v = ip[(size_t)c * 16384];
                asm("cvt.rna.tf32.f32 %0, %1;" : "=r"(tv) : "f"(v));
                dst[c * 132] = __uint_as_float(tv);
            }
        }
        __syncthreads();

        const int dy = ir - yw;
        if (dy < -1 || dy > 1) continue;               // warp-uniform (row_sel-uniform)

#pragma unroll
        for (int dx = -1; dx <= 1; dx++) {
            const int t = (dy + 1) * 3 + (dx + 1);
            float g[2][2];
#pragma unroll
            for (int mi = 0; mi < 2; mi++) {
                g[mi][0] = ((s_mbits[row_sel * 128 + px0 + mi * 16 + rr]     >> t) & 1) ? 1.f : 0.f;
                g[mi][1] = ((s_mbits[row_sel * 128 + px0 + mi * 16 + rr + 8] >> t) & 1) ? 1.f : 0.f;
            }
#pragma unroll
            for (int kk = 0; kk < 8; kk++) {
                const int c0 = kk * 8 + cc;
                uint32_t a[2][4];
#pragma unroll
                for (int mi = 0; mi < 2; mi++) {
                    int col = px0 + mi * 16 + rr + dx + 1;
                    float a0 = As[c0 * 132 + col]           * g[mi][0];
                    float a1 = As[c0 * 132 + col + 8]       * g[mi][1];
                    float a2 = As[(c0 + 4) * 132 + col]     * g[mi][0];
                    float a3 = As[(c0 + 4) * 132 + col + 8] * g[mi][1];
                    a[mi][0] = __float_as_uint(a0); a[mi][1] = __float_as_uint(a1);
                    a[mi][2] = __float_as_uint(a2); a[mi][3] = __float_as_uint(a3);
                }
                const float2* bf = g_bf + ((t * 8 + kk) * 8) * 32 + lane;
#pragma unroll
                for (int ni = 0; ni < 8; ni++) {
                    float2 bv = bf[ni * 32];
                    uint32_t b0 = __float_as_uint(bv.x), b1 = __float_as_uint(bv.y);
                    mma_tf32(acc[0][ni], a[0], b0, b1);
                    mma_tf32(acc[1][ni], a[1], b0, b1);
                }
            }
        }
    }

    // ---- epilogue: 4 groups of 16 oc; both rows staged in disjoint As halves ----
#pragma unroll
    for (int og = 0; og < 4; og++) {
        __syncthreads();
#pragma unroll
        for (int mi = 0; mi < 2; mi++)
#pragma unroll
            for (int nj = 0; nj < 2; nj++) {
                int ni = og * 2 + nj;
#pragma unroll
                for (int r = 0; r < 4; r++) {
                    int px  = px0 + mi * 16 + rr + ((r & 2) ? 8 : 0);
                    int ocl = nj * 8 + 2 * cc + (r & 1);
                    As[(row_sel * 16 + ocl) * 132 + px] = acc[mi][ni][r];
                }
            }
        __syncthreads();
        {
            const int px = tid & 127, prow = tid >> 7;
#pragma unroll
            for (int ocl = 0; ocl < 16; ocl++) {
                int oc = og * 16 + ocl;
                out[(((size_t)b * 64 + oc) * 128 + y0 + prow) * 128 + px] =
                    As[(prow * 16 + ocl) * 132 + px] * s_nrm[tid] + s_bias[oc];
            }
        }
    }
}

extern "C" void kernel_launch(void* const* d_in, const int* in_sizes, int n_in,
                              void* d_out, int out_size) {
    const float* inp  = (const float*)d_in[0];   // [8,64,128,128]
    const float* mask = (const float*)d_in[1];   // [8,128,128]
    const float* conv = (const float*)d_in[2];   // [64,64,3,3]
    const float* bias = (const float*)d_in[3];   // [64]
    float* out  = (float*)d_out;                 // [8,64,128,128] then mask_out
    float* mout = out + (size_t)BATCH * 64 * 128 * 128;

    prep_w<<<72, 256>>>(conv);
    iconv_mma<<<BATCH * 64, 256>>>(inp, mask, bias, out, mout);
}